// round 17
// baseline (speedup 1.0000x reference)
#include <cuda_runtime.h>
#include <cstdint>

// SobelLoss: loss = sum_{voxels,d in {x,y,z}} |conv_d(moved - label)| / (3*N)
// Shapes: (B=2, 1, D=160, H=192, W=160) fp32, zero padding.
// Sobel separable: S=[1,2,1] smooth, D=[-1,0,1] derivative.
//
// This version: cp.async (LDGSTS) pipeline — gmem->smem with NO register
// staging and NO consumer stalls; 2 planes in flight (commit/wait_group).
// m and l tiles live in smem; diff folds into the stencil by linearity
// (one packed subtract per loaded pair). Compute: 2 out-cols (f32x2 col
// packing + pmid shifts) x 2 out-rows (4-raw-row amortized) per thread.
// All boundary handling (x/y/z halos) via cp.async src-size=0 zero-fill.
// NBUF=4 buffers (m+l) = 23KB -> 8 CTAs/SM, 1200 CTAs = one wave.

typedef unsigned long long ull;

#define DIMX 160
#define DIMY 192
#define DIMZ 160
#define NBATCH 2
#define PLANE (DIMY * DIMX)

#define TXP 16                  // threads x (2 output cols each)
#define TY 8                    // threads y (2 output rows each)
#define NT (TXP * TY)           // 128
#define OX 32
#define OY 16
#define ZCHUNK 16
#define NZCH (DIMZ / ZCHUNK)    // 10

#define TILE_W 40               // raw cols: gx in [32bx-4, 32bx+35], quad-aligned
#define TILE_H 18               // raw rows
#define TILE_FLOATS (TILE_H * TILE_W)   // 720
#define NQ 10                   // col quads per row
#define NSLOT (TILE_H * NQ)     // 180 copy slots (16B each)
#define NBUF 4

#define GRID_X (DIMX / OX)      // 5
#define GRID_Y (DIMY / OY)      // 12
#define TOTAL_CTAS (GRID_X * GRID_Y * NBATCH * NZCH)   // 1200

// 1 / (3 * B*D*H*W) = 1 / 29491200
#define SCALE 3.3908420632258286e-08f
#define ABSM 0x7FFFFFFF7FFFFFFFULL

__device__ float    g_acc = 0.0f;
__device__ unsigned g_cnt = 0;

// ---- packed f32x2 helpers (Blackwell sm_103a) ----
__device__ __forceinline__ ull pk(float lo, float hi) {
    ull r; asm("mov.b64 %0, {%1, %2};" : "=l"(r) : "f"(lo), "f"(hi)); return r;
}
__device__ __forceinline__ void upk(ull p, float& lo, float& hi) {
    asm("mov.b64 {%0, %1}, %2;" : "=f"(lo), "=f"(hi) : "l"(p));
}
__device__ __forceinline__ ull padd(ull a, ull b) {
    ull r; asm("add.rn.f32x2 %0, %1, %2;" : "=l"(r) : "l"(a), "l"(b)); return r;
}
__device__ __forceinline__ ull pfma(ull a, ull b, ull c) {   // a*b + c
    ull r; asm("fma.rn.f32x2 %0, %1, %2, %3;" : "=l"(r) : "l"(a), "l"(b), "l"(c)); return r;
}
// (hi(a), lo(b))
__device__ __forceinline__ ull pmid(ull a, ull b) {
    float alo, ahi, blo, bhi;
    upk(a, alo, ahi); upk(b, blo, bhi);
    return pk(ahi, blo);
}

__device__ __forceinline__ uint32_t smem_u32(const void* p) {
    return (uint32_t)__cvta_generic_to_shared(p);
}
__device__ __forceinline__ void cpa16(uint32_t dst, const float* src, int ok) {
    asm volatile("cp.async.cg.shared.global [%0], [%1], 16, %2;"
                 :: "r"(dst), "l"(src), "r"(ok ? 16 : 0) : "memory");
}
#define CP_COMMIT() asm volatile("cp.async.commit_group;" ::: "memory")
#define CP_WAIT(n)  asm volatile("cp.async.wait_group %0;" :: "n"(n) : "memory")

__launch_bounds__(NT, 8)   // <=64 regs -> 8 CTAs/SM -> 1200 grid = ONE wave
__global__ void sobel_loss_kernel(const float* __restrict__ moved,
                                  const float* __restrict__ label,
                                  float* __restrict__ out)
{
    // [buf][array(m=0,l=1)][row*40+col], row-major fp32
    __shared__ __align__(16) float tiles[NBUF][2][TILE_FLOATS];

    const int tid = threadIdx.x;
    const int txp = tid & (TXP - 1);   // 0..15
    const int ty  = tid >> 4;          // 0..7

    const int b  = blockIdx.z / NZCH;
    const int z0 = (blockIdx.z % NZCH) * ZCHUNK;
    const int gx0 = blockIdx.x * OX - 4;   // quad-aligned
    const int gy0 = blockIdx.y * OY - 1;

    const float* mb = moved + (size_t)b * DIMZ * PLANE;
    const float* lb = label + (size_t)b * DIMZ * PLANE;

    const ull C2  = pk(2.0f, 2.0f);
    const ull CM1 = pk(-1.0f, -1.0f);

    // ---- copy slots: slot s -> (row s/10, quad s%10), 16B per array ----
    const int  row0 = tid / NQ, q0 = tid - (tid / NQ) * NQ;   // slot tid (<180 always)
    const int  gyA  = gy0 + row0, gxA = gx0 + 4 * q0;
    const bool okA  = ((unsigned)gyA < (unsigned)DIMY) && ((unsigned)gxA < (unsigned)DIMX);
    const int  offA = okA ? (gyA * DIMX + gxA) : 0;
    const uint32_t dA = smem_u32(&tiles[0][0][row0 * TILE_W + 4 * q0]);

    const int  s1   = tid + NT;                                // 128..255
    const bool has1 = (s1 < NSLOT);
    const int  row1 = s1 / NQ, q1 = s1 - (s1 / NQ) * NQ;
    const int  gyB  = gy0 + row1, gxB = gx0 + 4 * q1;
    const bool okB  = has1 && ((unsigned)gyB < (unsigned)DIMY) && ((unsigned)gxB < (unsigned)DIMX);
    const int  offB = okB ? (gyB * DIMX + gxB) : 0;
    const uint32_t dB = smem_u32(&tiles[0][0][(has1 ? (row1 * TILE_W + 4 * q1) : 0)]);

    const uint32_t BUFSTRIDE = 2u * TILE_FLOATS * 4u;   // 5760 B
    const uint32_t ARRSTRIDE = (uint32_t)TILE_FLOATS * 4u;   // 2880 B

    auto issue = [&](int j) {
        const int  zz  = z0 + j;
        const bool zok = ((unsigned)zz < (unsigned)DIMZ);
        const float* mz = mb + (size_t)(zok ? zz : 0) * PLANE;
        const float* lz = lb + (size_t)(zok ? zz : 0) * PLANE;
        const uint32_t bofs = (uint32_t)(j & 3) * BUFSTRIDE;
        const int oA = (zok && okA) ? 1 : 0;
        const int oB = (zok && okB) ? 1 : 0;
        cpa16(dA + bofs,             mz + offA, oA);
        cpa16(dA + bofs + ARRSTRIDE, lz + offA, oA);
        cpa16(dB + bofs,             mz + offB, oB);
        cpa16(dB + bofs + ARRSTRIDE, lz + offB, oB);
        CP_COMMIT();
    };

    // ---- stencil: 2 out cols (packed) x 2 out rows, diff via linearity ----
    // out cols global 32bx+2txp, +1 -> raw cols 2txp+4, +5; need raw 2txp+3..+6
    // ull (col-pair) index base: (2txp+2)/2 = txp+1 -> pairs at cols
    // (2txp+2,3), (2txp+4,5), (2txp+6,7). Shifts via pmid.
    const int cbase = txp + 1;

    auto pqr6 = [&](int buf,
                    ull& pA, ull& qA, ull& rA,
                    ull& pB, ull& qB, ull& rB) {
        ull s[4], d[4];
        #pragma unroll
        for (int r = 0; r < 4; r++) {
            const ull* mrow = (const ull*)&tiles[buf][0][(2 * ty + r) * TILE_W] + cbase;
            const ull* lrow = (const ull*)&tiles[buf][1][(2 * ty + r) * TILE_W] + cbase;
            ull v0 = pfma(lrow[0], CM1, mrow[0]);   // diff cols (c-2,c-1)
            ull v1 = pfma(lrow[1], CM1, mrow[1]);   // (c,c+1)
            ull v2 = pfma(lrow[2], CM1, mrow[2]);   // (c+2,c+3)
            ull vl = pmid(v0, v1);                  // (c-1,c)
            ull vr = pmid(v1, v2);                  // (c+1,c+2)
            s[r] = padd(pfma(v1, C2, vl), vr);      // Sx for out cols (c,c+1)
            d[r] = pfma(vl, CM1, vr);               // Dx
        }
        qA = pfma(s[0], CM1, s[2]);
        rA = padd(pfma(s[1], C2, s[0]), s[2]);
        pA = padd(pfma(d[1], C2, d[0]), d[2]);
        qB = pfma(s[1], CM1, s[3]);
        rB = padd(pfma(s[2], C2, s[1]), s[3]);
        pB = padd(pfma(d[2], C2, d[1]), d[3]);
    };

    ull pA0,qA0,rA0, pA1,qA1,rA1, pB0,qB0,rB0, pB1,qB1,rB1;
    ull acc = 0;

    // ---- pipeline prologue: planes z0-1, z0 in flight ----
    issue(-1);                    // group: plane -1  -> buf 3
    issue(0);                     // group: plane 0   -> buf 0

    // j = -1: compute pqr(plane -1)
    issue(1);                     // plane 1 -> buf 1
    CP_WAIT(2); __syncthreads();
    pqr6(3, pA0,qA0,rA0, pB0,qB0,rB0);

    // j = 0: compute pqr(plane 0)
    issue(2);                     // plane 2 -> buf 2
    CP_WAIT(2); __syncthreads();
    pqr6(0, pA1,qA1,rA1, pB1,qB1,rB1);

    #define EMITP(P0,P1,Q0,Q1,R0,R1, P2,Q2,R2)                             \
        do {                                                               \
            ull Gx = padd(pfma(P1, C2, P0), P2);                           \
            ull Gy = padd(pfma(Q1, C2, Q0), Q2);                           \
            ull Gz = pfma(R0, CM1, R2);                                    \
            acc = padd(acc, Gx & ABSM);                                    \
            acc = padd(acc, Gy & ABSM);                                    \
            acc = padd(acc, Gz & ABSM);                                    \
            P0 = P1; P1 = P2; Q0 = Q1; Q1 = Q2; R0 = R1; R1 = R2;          \
        } while (0)

    #define BODY(J)                                                        \
        do {                                                               \
            ull p2A,q2A,r2A, p2B,q2B,r2B;                                  \
            pqr6((J) & 3, p2A,q2A,r2A, p2B,q2B,r2B);                       \
            EMITP(pA0,pA1,qA0,qA1,rA0,rA1, p2A,q2A,r2A);                   \
            EMITP(pB0,pB1,qB0,qB1,rB0,rB1, p2B,q2B,r2B);                   \
        } while (0)

    // ---- main loop: j = 1 .. ZCHUNK-2 (issue plane j+2, 2 groups in flight)
    // buf (j+2)&3 held plane j-2: its reads (iter j-2) precede sync(j-1). Safe.
    #pragma unroll 2
    for (int j = 1; j <= ZCHUNK - 2; ++j) {
        issue(j + 2);
        CP_WAIT(2); __syncthreads();
        BODY(j);
    }
    // j = ZCHUNK-1: last commit was plane ZCHUNK -> 1 group may remain pending
    CP_WAIT(1); __syncthreads();
    BODY(ZCHUNK - 1);
    // j = ZCHUNK: all groups must be done
    CP_WAIT(0); __syncthreads();
    BODY(ZCHUNK);

    #undef BODY
    #undef EMITP

    // ---- reduce: packed -> scalar -> warp -> block -> global ----
    float lo, hi;
    upk(acc, lo, hi);
    float a = lo + hi;

    #pragma unroll
    for (int o = 16; o > 0; o >>= 1)
        a += __shfl_down_sync(0xFFFFFFFFu, a, o);

    __shared__ float wsum[NT / 32];
    if ((tid & 31) == 0) wsum[tid >> 5] = a;
    __syncthreads();

    if (tid < (NT / 32)) {
        float v = wsum[tid];
        #pragma unroll
        for (int o = (NT / 64); o > 0; o >>= 1)
            v += __shfl_down_sync(0xFu, v, o);
        if (tid == 0) {
            atomicAdd(&g_acc, v);
            __threadfence();
            if (atomicAdd(&g_cnt, 1u) == TOTAL_CTAS - 1) {
                __threadfence();
                *out = g_acc * SCALE;
                g_acc = 0.0f;      // reset for next (graph-replayed) launch
                g_cnt = 0;
            }
        }
    }
}

extern "C" void kernel_launch(void* const* d_in, const int* in_sizes, int n_in,
                              void* d_out, int out_size)
{
    const float* moved = (const float*)d_in[0];
    const float* label = (const float*)d_in[1];
    float* out = (float*)d_out;

    dim3 grid(GRID_X, GRID_Y, NBATCH * NZCH);   // (5, 12, 20) = 1200 CTAs
    sobel_loss_kernel<<<grid, NT>>>(moved, label, out);
}